// round 3
// baseline (speedup 1.0000x reference)
#include <cuda_runtime.h>
#include <math.h>

#define NEARV 0.01f
#define BLURV 0.3f
#define MAXA  0.999f
#define TQ    36.0f        // cull threshold: exp(-18) ~ 1.5e-8 max dropped alpha
#define MAXG  8192         // max C*N
#define MAXN  4096         // max N per camera (sort smem)
#define NCHUNK 8
#define MAXPIX 131072      // max C*H*W

// Scratch. record (3 x float4): f0=(m2x,m2y,ia,ib) f1=(ic,op,colR,colG) f2=(colB,bx,by,0)
__device__ float4 g_rec4[MAXG * 3];
__device__ float4 g_srec4[MAXG * 3];
__device__ float4 g_seg[NCHUNK * MAXPIX];   // per-chunk (r,g,b,T) per pixel

// ---------------------------------------------------------------------------
// K1: fused projection + conic + cull-bbox + stable depth sort (one block/cam)
// ---------------------------------------------------------------------------
__global__ void __launch_bounds__(1024)
k_presort(const float* __restrict__ vms, const float* __restrict__ Ks,
          const float* __restrict__ means, const float* __restrict__ quats,
          const float* __restrict__ lscales, const float* __restrict__ olog,
          const float* __restrict__ clog, int C, int N) {
    __shared__ float stz[MAXN];
    int cam = blockIdx.x;

    const float* vm = vms + cam * 16;
    const float* K  = Ks  + cam * 9;
    float fx = K[0], fy = K[4], cx = K[2], cy = K[5];
    float W00 = vm[0], W01 = vm[1], W02 = vm[2],  t0 = vm[3];
    float W10 = vm[4], W11 = vm[5], W12 = vm[6],  t1 = vm[7];
    float W20 = vm[8], W21 = vm[9], W22 = vm[10], t2 = vm[11];

    // --- projection phase: thread handles gaussians tid, tid+1024, ... ---
    for (int i = threadIdx.x; i < N; i += 1024) {
        float mx = means[i*3], my = means[i*3+1], mz = means[i*3+2];
        float tcx = W00*mx + W01*my + W02*mz + t0;
        float tcy = W10*mx + W11*my + W12*mz + t1;
        float tcz = W20*mx + W21*my + W22*mz + t2;

        float tzs = tcz > NEARV ? tcz : NEARV;
        float iz  = 1.0f / tzs;
        float m2x = fx * tcx * iz + cx;
        float m2y = fy * tcy * iz + cy;

        float qw = quats[i*4], qx = quats[i*4+1], qy = quats[i*4+2], qz = quats[i*4+3];
        float qn = rsqrtf(qw*qw + qx*qx + qy*qy + qz*qz);
        qw *= qn; qx *= qn; qy *= qn; qz *= qn;
        float R00 = 1.f - 2.f*(qy*qy + qz*qz), R01 = 2.f*(qx*qy - qw*qz), R02 = 2.f*(qx*qz + qw*qy);
        float R10 = 2.f*(qx*qy + qw*qz), R11 = 1.f - 2.f*(qx*qx + qz*qz), R12 = 2.f*(qy*qz - qw*qx);
        float R20 = 2.f*(qx*qz - qw*qy), R21 = 2.f*(qy*qz + qw*qx), R22 = 1.f - 2.f*(qx*qx + qy*qy);

        float s0 = __expf(lscales[i*3]), s1 = __expf(lscales[i*3+1]), s2 = __expf(lscales[i*3+2]);

        float ja = fx * iz;
        float jc = -fx * tcx * iz * iz;
        float jb = fy * iz;
        float jd = -fy * tcy * iz * iz;

        float JW00 = ja*W00 + jc*W20, JW01 = ja*W01 + jc*W21, JW02 = ja*W02 + jc*W22;
        float JW10 = jb*W10 + jd*W20, JW11 = jb*W11 + jd*W21, JW12 = jb*W12 + jd*W22;

        float U00 = (JW00*R00 + JW01*R10 + JW02*R20) * s0;
        float U01 = (JW00*R01 + JW01*R11 + JW02*R21) * s1;
        float U02 = (JW00*R02 + JW01*R12 + JW02*R22) * s2;
        float U10 = (JW10*R00 + JW11*R10 + JW12*R20) * s0;
        float U11 = (JW10*R01 + JW11*R11 + JW12*R21) * s1;
        float U12 = (JW10*R02 + JW11*R12 + JW12*R22) * s2;

        float ca = U00*U00 + U01*U01 + U02*U02 + BLURV;
        float cc = U10*U10 + U11*U11 + U12*U12 + BLURV;
        float cb = U00*U10 + U01*U11 + U02*U12;

        float det = ca*cc - cb*cb;
        bool valid = (tcz > NEARV) && (det > 1e-12f);

        float op = 1.0f / (1.0f + __expf(-olog[i]));
        float ia = 0.f, ib = 0.f, ic = 0.f, bx = 0.f, by = 0.f;
        if (valid) {
            float idet = 1.0f / det;
            ia = cc * idet; ib = -cb * idet; ic = ca * idet;
            bx = sqrtf(TQ * ca);
            by = sqrtf(TQ * cc);
        } else {
            op = 0.0f;
            m2x = -1e8f; m2y = -1e8f;   // bbox never overlaps any tile -> culled
        }

        float colr = 1.0f / (1.0f + __expf(-clog[i*3]));
        float colg = 1.0f / (1.0f + __expf(-clog[i*3+1]));
        float colb = 1.0f / (1.0f + __expf(-clog[i*3+2]));

        int t = cam * N + i;
        g_rec4[t*3 + 0] = make_float4(m2x, m2y, ia, ib);
        g_rec4[t*3 + 1] = make_float4(ic, op, colr, colg);
        g_rec4[t*3 + 2] = make_float4(colb, bx, by, 0.f);
        stz[i] = tcz;
    }
    __syncthreads();

    // --- stable rank-count sort from smem (broadcast reads) ---
    for (int i = threadIdx.x; i < N; i += 1024) {
        float ti = stz[i];
        int rank = 0;
        #pragma unroll 4
        for (int j = 0; j < N; j++) {
            float tj = stz[j];
            rank += (tj < ti) || (tj == ti && j < i);
        }
        int src = (cam * N + i) * 3, dst = (cam * N + rank) * 3;
        g_srec4[dst]   = g_rec4[src];
        g_srec4[dst+1] = g_rec4[src+1];
        g_srec4[dst+2] = g_rec4[src+2];
    }
}

// ---------------------------------------------------------------------------
// K2: tiled compositing over one depth chunk, ballot-compacted culling
// ---------------------------------------------------------------------------
#define TILE 16

__global__ void __launch_bounds__(256)
k_render(int C, int N, int W, int H) {
    __shared__ float4 sA[256], sB[256], sC[256];
    __shared__ int s_off[9];

    int zz = blockIdx.z;
    int cam = zz / NCHUNK, chunk = zz - cam * NCHUNK;
    int L  = (N + NCHUNK - 1) / NCHUNK;
    int gs = chunk * L, ge = min(N, gs + L);

    int tid = threadIdx.x, lane = tid & 31, wid = tid >> 5;
    int x = blockIdx.x * TILE + (tid & 15);
    int y = blockIdx.y * TILE + (tid >> 4);
    bool inside = (x < W) && (y < H);
    float pxf = x + 0.5f, pyf = y + 0.5f;

    float tx0 = blockIdx.x * TILE + 0.5f, tx1 = tx0 + (TILE - 1);
    float ty0 = blockIdx.y * TILE + 0.5f, ty1 = ty0 + (TILE - 1);

    float T = inside ? 1.0f : 0.0f;
    float aR = 0.f, aG = 0.f, aB = 0.f;
    int base = cam * N;

    for (int b0 = gs; b0 < ge; b0 += 256) {
        int gi = b0 + tid;
        bool keep = false;
        float4 f0, f2;
        if (gi < ge) {
            f0 = g_srec4[(base + gi) * 3];
            f2 = g_srec4[(base + gi) * 3 + 2];
            keep = (f0.x - f2.y <= tx1) && (f0.x + f2.y >= tx0) &&
                   (f0.y - f2.z <= ty1) && (f0.y + f2.z >= ty0);
        }
        unsigned m = __ballot_sync(0xffffffffu, keep);
        if (lane == 0) s_off[wid] = __popc(m);
        __syncthreads();
        if (tid == 0) {
            int acc = 0;
            #pragma unroll
            for (int w = 0; w < 8; w++) { int c = s_off[w]; s_off[w] = acc; acc += c; }
            s_off[8] = acc;
        }
        __syncthreads();
        if (keep) {
            float4 f1 = g_srec4[(base + gi) * 3 + 1];
            int pos = s_off[wid] + __popc(m & ((1u << lane) - 1));
            sA[pos] = f0; sB[pos] = f1; sC[pos] = f2;
        }
        int cnt = s_off[8];
        __syncthreads();

        // branchless front-to-back compositing over compacted, ordered list
        #pragma unroll 2
        for (int k = 0; k < cnt; k++) {
            float4 a = sA[k], b = sB[k], c = sC[k];
            float dx = pxf - a.x, dy = pyf - a.y;
            float q  = a.z*dx*dx + 2.0f*a.w*dx*dy + b.x*dy*dy;
            float al = fminf(b.y * __expf(-0.5f * q), MAXA);
            float w  = al * T;
            aR += w * b.z; aG += w * b.w; aB += w * c.x;
            T *= 1.0f - al;
        }
        if (b0 + 256 < ge) {
            if (__syncthreads_and(T < 1e-5f)) break;   // chunk-local early out
        }
    }

    if (inside) {
        int pix = (cam * H + y) * W + x;
        g_seg[chunk * MAXPIX + pix] = make_float4(aR, aG, aB, T);
    }
}

// ---------------------------------------------------------------------------
// K3: combine depth chunks per pixel (over-operator is associative)
// ---------------------------------------------------------------------------
__global__ void k_combine(float* __restrict__ out, int total) {
    int p = blockIdx.x * blockDim.x + threadIdx.x;
    if (p >= total) return;
    float T = 1.f, r = 0.f, g = 0.f, b = 0.f;
    #pragma unroll
    for (int s = 0; s < NCHUNK; s++) {
        float4 v = g_seg[s * MAXPIX + p];
        r += T * v.x; g += T * v.y; b += T * v.z;
        T *= v.w;
    }
    out[p*3] = r; out[p*3+1] = g; out[p*3+2] = b;
}

// ---------------------------------------------------------------------------
extern "C" void kernel_launch(void* const* d_in, const int* in_sizes, int n_in,
                              void* d_out, int out_size) {
    const float* vms   = (const float*)d_in[0];  // (C,4,4)
    const float* Ks    = (const float*)d_in[1];  // (C,3,3)
    const float* means = (const float*)d_in[2];  // (N,3)
    const float* quats = (const float*)d_in[3];  // (N,4)
    const float* lsc   = (const float*)d_in[4];  // (N,3)
    const float* olog  = (const float*)d_in[5];  // (N,)
    const float* clog  = (const float*)d_in[6];  // (N,3)

    int C = in_sizes[0] / 16;
    int N = in_sizes[2] / 3;
    int HW = out_size / (3 * C);
    int W = (int)(sqrt((double)HW) + 0.5);
    int H = HW / W;

    k_presort<<<C, 1024>>>(vms, Ks, means, quats, lsc, olog, clog, C, N);
    dim3 grender((W + TILE - 1) / TILE, (H + TILE - 1) / TILE, C * NCHUNK);
    k_render<<<grender, 256>>>(C, N, W, H);
    k_combine<<<(C * H * W + 127) / 128, 128>>>((float*)d_out, C * H * W);
}

// round 4
// speedup vs baseline: 1.8382x; 1.8382x over previous
#include <cuda_runtime.h>
#include <math.h>

#define NEARV 0.01f
#define BLURV 0.3f
#define MAXA  0.999f
#define TQ    36.0f        // cull threshold: exp(-18) ~ 1.5e-8 max dropped alpha
#define MAXG  8192         // max C*N
#define MAXN  4096         // max N per camera (sort smem)
#define NCHUNK 8
#define MAXPIX 131072      // max C*H*W
#define MAXTILE 4096       // max C * tilesX * tilesY

// Scratch. record (3 x float4): f0=(m2x,m2y,ia,ib) f1=(ic,op,colR,colG) f2=(colB,bx,by,0)
__device__ float  g_tz[MAXG];
__device__ float4 g_rec4[MAXG * 3];
__device__ float4 g_srec4[MAXG * 3];
__device__ float4 g_seg[NCHUNK * MAXPIX];   // per-chunk (r,g,b,T) per pixel
__device__ int    g_ctr[MAXTILE];           // ticket counters (zero-init, self-resetting)

// ---------------------------------------------------------------------------
// K1: per (camera, gaussian) projection + conic + cull bbox
// ---------------------------------------------------------------------------
__global__ void k_pre(const float* __restrict__ vms, const float* __restrict__ Ks,
                      const float* __restrict__ means, const float* __restrict__ quats,
                      const float* __restrict__ lscales, const float* __restrict__ olog,
                      const float* __restrict__ clog, int C, int N) {
    int t = blockIdx.x * blockDim.x + threadIdx.x;
    if (t >= C * N) return;
    int cam = t / N, i = t - cam * N;

    const float* vm = vms + cam * 16;
    const float* K  = Ks  + cam * 9;
    float fx = K[0], fy = K[4], cx = K[2], cy = K[5];

    float W00 = vm[0], W01 = vm[1], W02 = vm[2],  t0 = vm[3];
    float W10 = vm[4], W11 = vm[5], W12 = vm[6],  t1 = vm[7];
    float W20 = vm[8], W21 = vm[9], W22 = vm[10], t2 = vm[11];

    float mx = means[i*3], my = means[i*3+1], mz = means[i*3+2];
    float tcx = W00*mx + W01*my + W02*mz + t0;
    float tcy = W10*mx + W11*my + W12*mz + t1;
    float tcz = W20*mx + W21*my + W22*mz + t2;

    float tzs = tcz > NEARV ? tcz : NEARV;
    float iz  = 1.0f / tzs;
    float m2x = fx * tcx * iz + cx;
    float m2y = fy * tcy * iz + cy;

    float qw = quats[i*4], qx = quats[i*4+1], qy = quats[i*4+2], qz = quats[i*4+3];
    float qn = rsqrtf(qw*qw + qx*qx + qy*qy + qz*qz);
    qw *= qn; qx *= qn; qy *= qn; qz *= qn;
    float R00 = 1.f - 2.f*(qy*qy + qz*qz), R01 = 2.f*(qx*qy - qw*qz), R02 = 2.f*(qx*qz + qw*qy);
    float R10 = 2.f*(qx*qy + qw*qz), R11 = 1.f - 2.f*(qx*qx + qz*qz), R12 = 2.f*(qy*qz - qw*qx);
    float R20 = 2.f*(qx*qz - qw*qy), R21 = 2.f*(qy*qz + qw*qx), R22 = 1.f - 2.f*(qx*qx + qy*qy);

    float s0 = __expf(lscales[i*3]), s1 = __expf(lscales[i*3+1]), s2 = __expf(lscales[i*3+2]);

    float ja = fx * iz;
    float jc = -fx * tcx * iz * iz;
    float jb = fy * iz;
    float jd = -fy * tcy * iz * iz;

    float JW00 = ja*W00 + jc*W20, JW01 = ja*W01 + jc*W21, JW02 = ja*W02 + jc*W22;
    float JW10 = jb*W10 + jd*W20, JW11 = jb*W11 + jd*W21, JW12 = jb*W12 + jd*W22;

    float U00 = (JW00*R00 + JW01*R10 + JW02*R20) * s0;
    float U01 = (JW00*R01 + JW01*R11 + JW02*R21) * s1;
    float U02 = (JW00*R02 + JW01*R12 + JW02*R22) * s2;
    float U10 = (JW10*R00 + JW11*R10 + JW12*R20) * s0;
    float U11 = (JW10*R01 + JW11*R11 + JW12*R21) * s1;
    float U12 = (JW10*R02 + JW11*R12 + JW12*R22) * s2;

    float ca = U00*U00 + U01*U01 + U02*U02 + BLURV;
    float cc = U10*U10 + U11*U11 + U12*U12 + BLURV;
    float cb = U00*U10 + U01*U11 + U02*U12;

    float det = ca*cc - cb*cb;
    bool valid = (tcz > NEARV) && (det > 1e-12f);

    float op = 1.0f / (1.0f + __expf(-olog[i]));
    float ia = 0.f, ib = 0.f, ic = 0.f, bx = 0.f, by = 0.f;
    if (valid) {
        float idet = 1.0f / det;
        ia = cc * idet; ib = -cb * idet; ic = ca * idet;
        bx = sqrtf(TQ * ca);
        by = sqrtf(TQ * cc);
    } else {
        op = 0.0f;
        m2x = -1e8f; m2y = -1e8f;       // bbox never overlaps any tile -> culled
    }

    float colr = 1.0f / (1.0f + __expf(-clog[i*3]));
    float colg = 1.0f / (1.0f + __expf(-clog[i*3+1]));
    float colb = 1.0f / (1.0f + __expf(-clog[i*3+2]));

    g_tz[t] = tcz;
    g_rec4[t*3 + 0] = make_float4(m2x, m2y, ia, ib);
    g_rec4[t*3 + 1] = make_float4(ic, op, colr, colg);
    g_rec4[t*3 + 2] = make_float4(colb, bx, by, 0.f);
}

// ---------------------------------------------------------------------------
// K2: stable depth sort per camera via O(N^2) rank counting in smem
// ---------------------------------------------------------------------------
__global__ void k_sort(int N) {
    __shared__ float stz[MAXN];
    int cam = blockIdx.y;
    for (int i = threadIdx.x; i < N; i += blockDim.x) stz[i] = g_tz[cam * N + i];
    __syncthreads();
    int i = blockIdx.x * blockDim.x + threadIdx.x;
    if (i < N) {
        float ti = stz[i];
        int rank = 0;
        #pragma unroll 4
        for (int j = 0; j < N; j++) {
            float tj = stz[j];
            rank += (tj < ti) || (tj == ti && j < i);   // stable
        }
        int src = (cam * N + i) * 3, dst = (cam * N + rank) * 3;
        g_srec4[dst]   = g_rec4[src];
        g_srec4[dst+1] = g_rec4[src+1];
        g_srec4[dst+2] = g_rec4[src+2];
    }
}

// ---------------------------------------------------------------------------
// K3: tiled compositing over one depth chunk + last-block chunk combine
// ---------------------------------------------------------------------------
#define TILE 16

__global__ void __launch_bounds__(256)
k_render(float* __restrict__ out, int C, int N, int W, int H) {
    __shared__ float4 sA[256], sB[256], sC[256];
    __shared__ int s_off[9];
    __shared__ int s_last;

    int zz = blockIdx.z;
    int cam = zz / NCHUNK, chunk = zz - cam * NCHUNK;
    int L  = (N + NCHUNK - 1) / NCHUNK;
    int gs = chunk * L, ge = min(N, gs + L);

    int tid = threadIdx.x, lane = tid & 31, wid = tid >> 5;
    int x = blockIdx.x * TILE + (tid & 15);
    int y = blockIdx.y * TILE + (tid >> 4);
    bool inside = (x < W) && (y < H);
    float pxf = x + 0.5f, pyf = y + 0.5f;

    float tx0 = blockIdx.x * TILE + 0.5f, tx1 = tx0 + (TILE - 1);
    float ty0 = blockIdx.y * TILE + 0.5f, ty1 = ty0 + (TILE - 1);

    float T = inside ? 1.0f : 0.0f;
    float aR = 0.f, aG = 0.f, aB = 0.f;
    int base = cam * N;

    for (int b0 = gs; b0 < ge; b0 += 256) {
        int gi = b0 + tid;
        bool keep = false;
        float4 f0, f2;
        if (gi < ge) {
            f0 = g_srec4[(base + gi) * 3];
            f2 = g_srec4[(base + gi) * 3 + 2];
            keep = (f0.x - f2.y <= tx1) && (f0.x + f2.y >= tx0) &&
                   (f0.y - f2.z <= ty1) && (f0.y + f2.z >= ty0);
        }
        unsigned m = __ballot_sync(0xffffffffu, keep);
        if (lane == 0) s_off[wid] = __popc(m);
        __syncthreads();
        if (tid == 0) {
            int acc = 0;
            #pragma unroll
            for (int w = 0; w < 8; w++) { int c = s_off[w]; s_off[w] = acc; acc += c; }
            s_off[8] = acc;
        }
        __syncthreads();
        if (keep) {
            float4 f1 = g_srec4[(base + gi) * 3 + 1];
            int pos = s_off[wid] + __popc(m & ((1u << lane) - 1));
            sA[pos] = f0; sB[pos] = f1; sC[pos] = f2;
        }
        int cnt = s_off[8];
        __syncthreads();

        // branchless front-to-back compositing over compacted, ordered list
        #pragma unroll 2
        for (int k = 0; k < cnt; k++) {
            float4 a = sA[k], b = sB[k], c = sC[k];
            float dx = pxf - a.x, dy = pyf - a.y;
            float q  = a.z*dx*dx + 2.0f*a.w*dx*dy + b.x*dy*dy;
            float al = fminf(b.y * __expf(-0.5f * q), MAXA);
            float w  = al * T;
            aR += w * b.z; aG += w * b.w; aB += w * c.x;
            T *= 1.0f - al;
        }
        if (b0 + 256 < ge) {
            if (__syncthreads_and(T < 1e-5f)) break;   // chunk-local early out
        }
    }

    int pix = (cam * H + y) * W + x;
    if (inside)
        g_seg[chunk * MAXPIX + pix] = make_float4(aR, aG, aB, T);

    // ---- ticket: last chunk-block for this (cam,tile) combines all chunks ----
    __threadfence();
    int tilesX = gridDim.x, tilesY = gridDim.y;
    int tix = (cam * tilesY + blockIdx.y) * tilesX + blockIdx.x;
    if (tid == 0)
        s_last = (atomicAdd(&g_ctr[tix], 1) == NCHUNK - 1);
    __syncthreads();

    if (s_last) {
        if (inside) {
            float Tc = 1.f, r = 0.f, g = 0.f, b = 0.f;
            #pragma unroll
            for (int s = 0; s < NCHUNK; s++) {
                float4 v = g_seg[s * MAXPIX + pix];
                r += Tc * v.x; g += Tc * v.y; b += Tc * v.z;
                Tc *= v.w;
            }
            out[pix*3] = r; out[pix*3+1] = g; out[pix*3+2] = b;
        }
        if (tid == 0) g_ctr[tix] = 0;     // reset for next graph replay
    }
}

// ---------------------------------------------------------------------------
extern "C" void kernel_launch(void* const* d_in, const int* in_sizes, int n_in,
                              void* d_out, int out_size) {
    const float* vms   = (const float*)d_in[0];  // (C,4,4)
    const float* Ks    = (const float*)d_in[1];  // (C,3,3)
    const float* means = (const float*)d_in[2];  // (N,3)
    const float* quats = (const float*)d_in[3];  // (N,4)
    const float* lsc   = (const float*)d_in[4];  // (N,3)
    const float* olog  = (const float*)d_in[5];  // (N,)
    const float* clog  = (const float*)d_in[6];  // (N,3)

    int C = in_sizes[0] / 16;
    int N = in_sizes[2] / 3;
    int HW = out_size / (3 * C);
    int W = (int)(sqrt((double)HW) + 0.5);
    int H = HW / W;

    k_pre<<<(C * N + 127) / 128, 128>>>(vms, Ks, means, quats, lsc, olog, clog, C, N);
    dim3 gsort((N + 255) / 256, C);
    k_sort<<<gsort, 256>>>(N);
    dim3 grender((W + TILE - 1) / TILE, (H + TILE - 1) / TILE, C * NCHUNK);
    k_render<<<grender, 256>>>((float*)d_out, C, N, W, H);
}

// round 5
// speedup vs baseline: 2.0221x; 1.1000x over previous
#include <cuda_runtime.h>
#include <math.h>

#define NEARV 0.01f
#define BLURV 0.3f
#define MAXA  0.999f
#define TQ    36.0f        // cull threshold: exp(-18) ~ 1.5e-8 max dropped alpha
#define MAXG  8192         // max C*N
#define MAXN  4096         // max N per camera
#define NCHUNK 4
#define MAXPIX 131072      // max C*H*W
#define MAXTILE 4096       // max C * tilesX * tilesY
#define MAXC 8

// record (3 x float4): f0=(m2x,m2y,A,B) f1=(C,lop,colR,colG) f2=(colB,bx,by,0)
// alpha = ex2( A*dx^2 + B*dx*dy + C*dy^2 + lop )
__device__ float  g_tz[MAXG];
__device__ float4 g_rec4[MAXG * 3];
__device__ float4 g_srec4[MAXG * 3];
__device__ float4 g_seg[NCHUNK * MAXPIX];   // per-chunk (r,g,b,T) per pixel
__device__ int    g_ctr[MAXTILE];           // render ticket counters (self-reset)
__device__ int    g_done[MAXC];             // presort phase-A counters (self-reset)
__device__ int    g_pass[MAXC];             // presort phase-B counters (self-reset)

__device__ __forceinline__ float ex2(float x) {
    float r; asm("ex2.approx.ftz.f32 %0, %1;" : "=f"(r) : "f"(x)); return r;
}

// ---------------------------------------------------------------------------
// K1: fused projection/conic + stable depth sort. grid=(ceil(N/128), C),
// block=128. All C*ceil(N/128) blocks are co-resident (<=64 blocks), so a
// spin-based per-camera sync between phases is deadlock-free.
// ---------------------------------------------------------------------------
__global__ void __launch_bounds__(128)
k_presort(const float* __restrict__ vms, const float* __restrict__ Ks,
          const float* __restrict__ means, const float* __restrict__ quats,
          const float* __restrict__ lscales, const float* __restrict__ olog,
          const float* __restrict__ clog, int C, int N) {
    __shared__ float stz[MAXN];
    int cam = blockIdx.y;
    int B   = gridDim.x;
    int i   = blockIdx.x * 128 + threadIdx.x;

    const float* vm = vms + cam * 16;
    const float* K  = Ks  + cam * 9;
    float fx = K[0], fy = K[4], cx = K[2], cy = K[5];
    float W00 = vm[0], W01 = vm[1], W02 = vm[2],  t0 = vm[3];
    float W10 = vm[4], W11 = vm[5], W12 = vm[6],  t1 = vm[7];
    float W20 = vm[8], W21 = vm[9], W22 = vm[10], t2 = vm[11];

    if (i < N) {
        float mx = means[i*3], my = means[i*3+1], mz = means[i*3+2];
        float tcx = W00*mx + W01*my + W02*mz + t0;
        float tcy = W10*mx + W11*my + W12*mz + t1;
        float tcz = W20*mx + W21*my + W22*mz + t2;

        float tzs = tcz > NEARV ? tcz : NEARV;
        float iz  = 1.0f / tzs;
        float m2x = fx * tcx * iz + cx;
        float m2y = fy * tcy * iz + cy;

        float4 qv = ((const float4*)quats)[i];
        float qw = qv.x, qx = qv.y, qy = qv.z, qz = qv.w;
        float qn = rsqrtf(qw*qw + qx*qx + qy*qy + qz*qz);
        qw *= qn; qx *= qn; qy *= qn; qz *= qn;
        float R00 = 1.f - 2.f*(qy*qy + qz*qz), R01 = 2.f*(qx*qy - qw*qz), R02 = 2.f*(qx*qz + qw*qy);
        float R10 = 2.f*(qx*qy + qw*qz), R11 = 1.f - 2.f*(qx*qx + qz*qz), R12 = 2.f*(qy*qz - qw*qx);
        float R20 = 2.f*(qx*qz - qw*qy), R21 = 2.f*(qy*qz + qw*qx), R22 = 1.f - 2.f*(qx*qx + qy*qy);

        float s0 = __expf(lscales[i*3]), s1 = __expf(lscales[i*3+1]), s2 = __expf(lscales[i*3+2]);

        float ja = fx * iz;
        float jc = -fx * tcx * iz * iz;
        float jb = fy * iz;
        float jd = -fy * tcy * iz * iz;

        float JW00 = ja*W00 + jc*W20, JW01 = ja*W01 + jc*W21, JW02 = ja*W02 + jc*W22;
        float JW10 = jb*W10 + jd*W20, JW11 = jb*W11 + jd*W21, JW12 = jb*W12 + jd*W22;

        float U00 = (JW00*R00 + JW01*R10 + JW02*R20) * s0;
        float U01 = (JW00*R01 + JW01*R11 + JW02*R21) * s1;
        float U02 = (JW00*R02 + JW01*R12 + JW02*R22) * s2;
        float U10 = (JW10*R00 + JW11*R10 + JW12*R20) * s0;
        float U11 = (JW10*R01 + JW11*R11 + JW12*R21) * s1;
        float U12 = (JW10*R02 + JW11*R12 + JW12*R22) * s2;

        float ca = U00*U00 + U01*U01 + U02*U02 + BLURV;
        float cc = U10*U10 + U11*U11 + U12*U12 + BLURV;
        float cb = U00*U10 + U01*U11 + U02*U12;

        float det = ca*cc - cb*cb;
        bool valid = (tcz > NEARV) && (det > 1e-12f);

        float op = 1.0f / (1.0f + __expf(-olog[i]));
        const float HL2E = 0.72134752044f;   // 0.5*log2(e)
        float A = 0.f, Bc = 0.f, Cc = 0.f, lop = -1e30f, bx = 0.f, by = 0.f;
        if (valid) {
            float idet = 1.0f / det;
            A  = -HL2E * (cc * idet);
            Bc = 2.0f * HL2E * (cb * idet);   // -log2e * ib, ib = -cb*idet
            Cc = -HL2E * (ca * idet);
            lop = __log2f(op);
            bx = sqrtf(TQ * ca);
            by = sqrtf(TQ * cc);
        } else {
            m2x = -1e8f; m2y = -1e8f;        // bbox never overlaps -> culled
        }

        float colr = 1.0f / (1.0f + __expf(-clog[i*3]));
        float colg = 1.0f / (1.0f + __expf(-clog[i*3+1]));
        float colb = 1.0f / (1.0f + __expf(-clog[i*3+2]));

        int t = cam * N + i;
        g_tz[t] = tcz;
        g_rec4[t*3 + 0] = make_float4(m2x, m2y, A, Bc);
        g_rec4[t*3 + 1] = make_float4(Cc, lop, colr, colg);
        g_rec4[t*3 + 2] = make_float4(colb, bx, by, 0.f);
    }

    // ---- release: this block's records are written ----
    __threadfence();
    __syncthreads();
    if (threadIdx.x == 0) atomicAdd(&g_done[cam], 1);

    // ---- spin until all blocks of this camera finished phase A ----
    if (threadIdx.x == 0) {
        while (*((volatile int*)&g_done[cam]) < B) { }
    }
    __syncthreads();
    __threadfence();

    // ---- phase B: stable rank-count sort ----
    for (int j = threadIdx.x; j < N; j += 128) stz[j] = g_tz[cam * N + j];
    __syncthreads();

    if (i < N) {
        float ti = stz[i];
        int rank = 0;
        #pragma unroll 4
        for (int j = 0; j < N; j++) {
            float tj = stz[j];
            rank += (tj < ti) || (tj == ti && j < i);
        }
        int src = (cam * N + i) * 3, dst = (cam * N + rank) * 3;
        g_srec4[dst]   = g_rec4[src];
        g_srec4[dst+1] = g_rec4[src+1];
        g_srec4[dst+2] = g_rec4[src+2];
    }

    // ---- reset counters for next graph replay (last block per camera) ----
    __syncthreads();
    if (threadIdx.x == 0) {
        if (atomicAdd(&g_pass[cam], 1) == B - 1) {
            g_done[cam] = 0;
            g_pass[cam] = 0;
        }
    }
}

// ---------------------------------------------------------------------------
// K2: tiled compositing over one depth chunk + last-block chunk combine
// ---------------------------------------------------------------------------
#define TILE 16

__global__ void __launch_bounds__(256)
k_render(float* __restrict__ out, int C, int N, int W, int H) {
    __shared__ float4 sA[256], sB[256], sC[256];
    __shared__ int s_off[9];
    __shared__ int s_last;

    int zz = blockIdx.z;
    int cam = zz / NCHUNK, chunk = zz - cam * NCHUNK;
    int L  = (N + NCHUNK - 1) / NCHUNK;
    int gs = chunk * L, ge = min(N, gs + L);

    int tid = threadIdx.x, lane = tid & 31, wid = tid >> 5;
    int x = blockIdx.x * TILE + (tid & 15);
    int y = blockIdx.y * TILE + (tid >> 4);
    bool inside = (x < W) && (y < H);
    float pxf = x + 0.5f, pyf = y + 0.5f;

    float tx0 = blockIdx.x * TILE + 0.5f, tx1 = tx0 + (TILE - 1);
    float ty0 = blockIdx.y * TILE + 0.5f, ty1 = ty0 + (TILE - 1);

    float T = inside ? 1.0f : 0.0f;
    float aR = 0.f, aG = 0.f, aB = 0.f;
    int base = cam * N;

    for (int b0 = gs; b0 < ge; b0 += 256) {
        int gi = b0 + tid;
        bool keep = false;
        float4 f0, f2;
        if (gi < ge) {
            f0 = g_srec4[(base + gi) * 3];
            f2 = g_srec4[(base + gi) * 3 + 2];
            keep = (f0.x - f2.y <= tx1) && (f0.x + f2.y >= tx0) &&
                   (f0.y - f2.z <= ty1) && (f0.y + f2.z >= ty0);
        }
        unsigned m = __ballot_sync(0xffffffffu, keep);
        if (lane == 0) s_off[wid] = __popc(m);
        __syncthreads();
        if (tid == 0) {
            int acc = 0;
            #pragma unroll
            for (int w = 0; w < 8; w++) { int c = s_off[w]; s_off[w] = acc; acc += c; }
            s_off[8] = acc;
        }
        __syncthreads();
        if (keep) {
            float4 f1 = g_srec4[(base + gi) * 3 + 1];
            int pos = s_off[wid] + __popc(m & ((1u << lane) - 1));
            sA[pos] = f0; sB[pos] = f1; sC[pos] = f2;
        }
        int cnt = s_off[8];
        __syncthreads();

        // branchless front-to-back compositing; alpha in log2 domain
        #pragma unroll 2
        for (int k = 0; k < cnt; k++) {
            float4 a = sA[k], b = sB[k], c = sC[k];
            float dx = pxf - a.x, dy = pyf - a.y;
            float u  = a.z * dx + a.w * dy;
            float e2 = fmaf(u, dx, fmaf(b.x * dy, dy, b.y));
            float al = fminf(ex2(e2), MAXA);
            float w  = al * T;
            aR += w * b.z; aG += w * b.w; aB += w * c.x;
            T -= w;
        }
        if (b0 + 256 < ge) {
            if (__syncthreads_and(T < 1e-5f)) break;
        }
    }

    int pix = (cam * H + y) * W + x;
    if (inside)
        g_seg[chunk * MAXPIX + pix] = make_float4(aR, aG, aB, T);

    // ---- ticket: last chunk-block for this (cam,tile) combines all chunks ----
    __threadfence();
    int tilesX = gridDim.x, tilesY = gridDim.y;
    int tix = (cam * tilesY + blockIdx.y) * tilesX + blockIdx.x;
    if (tid == 0)
        s_last = (atomicAdd(&g_ctr[tix], 1) == NCHUNK - 1);
    __syncthreads();

    if (s_last) {
        if (inside) {
            float Tc = 1.f, r = 0.f, g = 0.f, b = 0.f;
            #pragma unroll
            for (int s = 0; s < NCHUNK; s++) {
                float4 v = g_seg[s * MAXPIX + pix];
                r += Tc * v.x; g += Tc * v.y; b += Tc * v.z;
                Tc *= v.w;
            }
            out[pix*3] = r; out[pix*3+1] = g; out[pix*3+2] = b;
        }
        if (tid == 0) g_ctr[tix] = 0;     // reset for next graph replay
    }
}

// ---------------------------------------------------------------------------
extern "C" void kernel_launch(void* const* d_in, const int* in_sizes, int n_in,
                              void* d_out, int out_size) {
    const float* vms   = (const float*)d_in[0];  // (C,4,4)
    const float* Ks    = (const float*)d_in[1];  // (C,3,3)
    const float* means = (const float*)d_in[2];  // (N,3)
    const float* quats = (const float*)d_in[3];  // (N,4)
    const float* lsc   = (const float*)d_in[4];  // (N,3)
    const float* olog  = (const float*)d_in[5];  // (N,)
    const float* clog  = (const float*)d_in[6];  // (N,3)

    int C = in_sizes[0] / 16;
    int N = in_sizes[2] / 3;
    int HW = out_size / (3 * C);
    int W = (int)(sqrt((double)HW) + 0.5);
    int H = HW / W;

    dim3 gpre((N + 127) / 128, C);
    k_presort<<<gpre, 128>>>(vms, Ks, means, quats, lsc, olog, clog, C, N);
    dim3 grender((W + TILE - 1) / TILE, (H + TILE - 1) / TILE, C * NCHUNK);
    k_render<<<grender, 256>>>((float*)d_out, C, N, W, H);
}

// round 6
// speedup vs baseline: 2.1024x; 1.0398x over previous
#include <cuda_runtime.h>
#include <math.h>

#define NEARV 0.01f
#define BLURV 0.3f
#define MAXA  0.999f
#define TQ    36.0f        // cull threshold: exp(-18) ~ 1.5e-8 max dropped alpha
#define MAXG  8192         // max C*N
#define MAXN  2048         // max N per camera (sort smem)
#define NCHUNK 4
#define MAXPIX 131072      // max C*H*W
#define MAXTILE 4096       // max C * tilesX * tilesY
#define TILE 16
#define NB 296             // persistent blocks: 2 per SM on 148 SMs (all co-resident)

// record (3 x float4): f0=(m2x,m2y,A,B) f1=(C,lop,colR,colG) f2=(colB,bx,by,0)
// alpha = ex2( A*dx^2 + B*dx*dy + C*dy^2 + lop )
__device__ float  g_tz[MAXG];
__device__ float4 g_rec4[MAXG * 3];
__device__ float4 g_srec4[MAXG * 3];
__device__ float4 g_seg[NCHUNK * MAXPIX];   // per-chunk (r,g,b,T) per pixel
__device__ int    g_ctr[MAXTILE];           // combine tickets (self-reset per tile)
__device__ int    g_bar;                    // monotonic grid barrier (reset at exit)
__device__ int    g_work;                   // work-queue head (reset at exit)

__device__ __forceinline__ float ex2(float x) {
    float r; asm("ex2.approx.ftz.f32 %0, %1;" : "=f"(r) : "f"(x)); return r;
}

// Monotonic spin barrier: all NB blocks co-resident -> deadlock-free.
__device__ __forceinline__ void grid_barrier(int target) {
    __syncthreads();
    if (threadIdx.x == 0) {
        __threadfence();
        atomicAdd(&g_bar, 1);
        while (*((volatile int*)&g_bar) < target) { }
        __threadfence();
    }
    __syncthreads();
}

__global__ void __launch_bounds__(256, 2)
k_fused(const float* __restrict__ vms, const float* __restrict__ Ks,
        const float* __restrict__ means, const float* __restrict__ quats,
        const float* __restrict__ lscales, const float* __restrict__ olog,
        const float* __restrict__ clog, float* __restrict__ out,
        int C, int N, int W, int H, int tilesX, int tilesY) {
    __shared__ float4 sA[256], sB[256];
    __shared__ float  sCb[256];
    __shared__ float  stz[MAXN];
    __shared__ int    s_off[9];
    __shared__ int    s_misc;   // item id / last flag

    int tid = threadIdx.x;
    int gid = blockIdx.x * 256 + tid;

    // ================= Phase A: projection + conic + cull bbox ==============
    if (gid < C * N) {
        int cam = gid / N, i = gid - cam * N;
        const float* vm = vms + cam * 16;
        const float* K  = Ks  + cam * 9;
        float fx = K[0], fy = K[4], cx = K[2], cy = K[5];
        float W00 = vm[0], W01 = vm[1], W02 = vm[2],  t0 = vm[3];
        float W10 = vm[4], W11 = vm[5], W12 = vm[6],  t1 = vm[7];
        float W20 = vm[8], W21 = vm[9], W22 = vm[10], t2 = vm[11];

        float mx = means[i*3], my = means[i*3+1], mz = means[i*3+2];
        float tcx = W00*mx + W01*my + W02*mz + t0;
        float tcy = W10*mx + W11*my + W12*mz + t1;
        float tcz = W20*mx + W21*my + W22*mz + t2;

        float tzs = tcz > NEARV ? tcz : NEARV;
        float iz  = 1.0f / tzs;
        float m2x = fx * tcx * iz + cx;
        float m2y = fy * tcy * iz + cy;

        float4 qv = ((const float4*)quats)[i];
        float qw = qv.x, qx = qv.y, qy = qv.z, qz = qv.w;
        float qn = rsqrtf(qw*qw + qx*qx + qy*qy + qz*qz);
        qw *= qn; qx *= qn; qy *= qn; qz *= qn;
        float R00 = 1.f - 2.f*(qy*qy + qz*qz), R01 = 2.f*(qx*qy - qw*qz), R02 = 2.f*(qx*qz + qw*qy);
        float R10 = 2.f*(qx*qy + qw*qz), R11 = 1.f - 2.f*(qx*qx + qz*qz), R12 = 2.f*(qy*qz - qw*qx);
        float R20 = 2.f*(qx*qz - qw*qy), R21 = 2.f*(qy*qz + qw*qx), R22 = 1.f - 2.f*(qx*qx + qy*qy);

        float s0 = __expf(lscales[i*3]), s1 = __expf(lscales[i*3+1]), s2 = __expf(lscales[i*3+2]);

        float ja = fx * iz;
        float jc = -fx * tcx * iz * iz;
        float jb = fy * iz;
        float jd = -fy * tcy * iz * iz;

        float JW00 = ja*W00 + jc*W20, JW01 = ja*W01 + jc*W21, JW02 = ja*W02 + jc*W22;
        float JW10 = jb*W10 + jd*W20, JW11 = jb*W11 + jd*W21, JW12 = jb*W12 + jd*W22;

        float U00 = (JW00*R00 + JW01*R10 + JW02*R20) * s0;
        float U01 = (JW00*R01 + JW01*R11 + JW02*R21) * s1;
        float U02 = (JW00*R02 + JW01*R12 + JW02*R22) * s2;
        float U10 = (JW10*R00 + JW11*R10 + JW12*R20) * s0;
        float U11 = (JW10*R01 + JW11*R11 + JW12*R21) * s1;
        float U12 = (JW10*R02 + JW11*R12 + JW12*R22) * s2;

        float ca = U00*U00 + U01*U01 + U02*U02 + BLURV;
        float cc = U10*U10 + U11*U11 + U12*U12 + BLURV;
        float cb = U00*U10 + U01*U11 + U02*U12;

        float det = ca*cc - cb*cb;
        bool valid = (tcz > NEARV) && (det > 1e-12f);

        float op = 1.0f / (1.0f + __expf(-olog[i]));
        const float HL2E = 0.72134752044f;   // 0.5*log2(e)
        float A = 0.f, Bc = 0.f, Cc = 0.f, lop = -1e30f, bx = 0.f, by = 0.f;
        if (valid) {
            float idet = 1.0f / det;
            A  = -HL2E * (cc * idet);
            Bc = 2.0f * HL2E * (cb * idet);
            Cc = -HL2E * (ca * idet);
            lop = __log2f(op);
            bx = sqrtf(TQ * ca);
            by = sqrtf(TQ * cc);
        } else {
            m2x = -1e8f; m2y = -1e8f;        // bbox never overlaps -> culled
        }

        float colr = 1.0f / (1.0f + __expf(-clog[i*3]));
        float colg = 1.0f / (1.0f + __expf(-clog[i*3+1]));
        float colb = 1.0f / (1.0f + __expf(-clog[i*3+2]));

        g_tz[gid] = tcz;
        g_rec4[gid*3 + 0] = make_float4(m2x, m2y, A, Bc);
        g_rec4[gid*3 + 1] = make_float4(Cc, lop, colr, colg);
        g_rec4[gid*3 + 2] = make_float4(colb, bx, by, 0.f);
    }

    grid_barrier(NB);

    // ================= Phase B: stable rank-count depth sort ================
    {
        int per = (N + 255) / 256;          // blocks per camera
        int sortBlocks = C * per;
        if (blockIdx.x < sortBlocks) {
            int cam = blockIdx.x / per;
            int i   = (blockIdx.x - cam * per) * 256 + tid;
            for (int j = tid; j < N; j += 256) stz[j] = g_tz[cam * N + j];
            __syncthreads();
            if (i < N) {
                float ti = stz[i];
                int rank = 0;
                #pragma unroll 4
                for (int j = 0; j < N; j++) {
                    float tj = stz[j];
                    rank += (tj < ti) || (tj == ti && j < i);
                }
                int src = (cam * N + i) * 3, dst = (cam * N + rank) * 3;
                g_srec4[dst]   = g_rec4[src];
                g_srec4[dst+1] = g_rec4[src+1];
                g_srec4[dst+2] = g_rec4[src+2];
            }
        }
    }

    grid_barrier(2 * NB);

    // ================= Phase C: dynamic-queue tiled compositing =============
    int total = tilesX * tilesY * C * NCHUNK;
    int L = (N + NCHUNK - 1) / NCHUNK;
    int lane = tid & 31, wid = tid >> 5;

    for (;;) {
        __syncthreads();
        if (tid == 0) s_misc = atomicAdd(&g_work, 1);
        __syncthreads();
        int item = s_misc;
        if (item >= total) break;

        int tmp = item;
        int chunk = tmp % NCHUNK; tmp /= NCHUNK;
        int cam   = tmp % C;      tmp /= C;
        int tx    = tmp % tilesX;
        int ty    = tmp / tilesX;

        int gs = chunk * L, ge = min(N, gs + L);
        int x = tx * TILE + (tid & 15);
        int y = ty * TILE + (tid >> 4);
        bool inside = (x < W) && (y < H);
        float pxf = x + 0.5f, pyf = y + 0.5f;
        float tx0 = tx * TILE + 0.5f, tx1 = tx0 + (TILE - 1);
        float ty0 = ty * TILE + 0.5f, ty1 = ty0 + (TILE - 1);

        float T = inside ? 1.0f : 0.0f;
        float aR = 0.f, aG = 0.f, aB = 0.f;
        int base = cam * N;

        for (int b0 = gs; b0 < ge; b0 += 256) {
            int gi = b0 + tid;
            bool keep = false;
            float4 f0, f2;
            if (gi < ge) {
                f0 = g_srec4[(base + gi) * 3];
                f2 = g_srec4[(base + gi) * 3 + 2];
                keep = (f0.x - f2.y <= tx1) && (f0.x + f2.y >= tx0) &&
                       (f0.y - f2.z <= ty1) && (f0.y + f2.z >= ty0);
            }
            unsigned m = __ballot_sync(0xffffffffu, keep);
            if (lane == 0) s_off[wid] = __popc(m);
            __syncthreads();
            if (tid == 0) {
                int acc = 0;
                #pragma unroll
                for (int w = 0; w < 8; w++) { int c = s_off[w]; s_off[w] = acc; acc += c; }
                s_off[8] = acc;
            }
            __syncthreads();
            if (keep) {
                float4 f1 = g_srec4[(base + gi) * 3 + 1];
                int pos = s_off[wid] + __popc(m & ((1u << lane) - 1));
                sA[pos] = f0; sB[pos] = f1; sCb[pos] = f2.x;
            }
            int cnt = s_off[8];
            __syncthreads();

            // branchless front-to-back compositing (alpha in log2 domain)
            #pragma unroll 2
            for (int k = 0; k < cnt; k++) {
                float4 a = sA[k], b = sB[k];
                float cb2 = sCb[k];
                float dx = pxf - a.x, dy = pyf - a.y;
                float u  = a.z * dx + a.w * dy;
                float e2 = fmaf(u, dx, fmaf(b.x * dy, dy, b.y));
                float al = fminf(ex2(e2), MAXA);
                float w  = al * T;
                aR += w * b.z; aG += w * b.w; aB += w * cb2;
                T -= w;
            }
            if (b0 + 256 < ge) {
                if (__syncthreads_and(T < 1e-5f)) break;
            }
        }

        int pix = (cam * H + y) * W + x;
        if (inside)
            g_seg[chunk * MAXPIX + pix] = make_float4(aR, aG, aB, T);

        // ---- ticket: last chunk for this (cam,tile) combines all chunks ----
        __threadfence();
        int tix = (cam * tilesY + ty) * tilesX + tx;
        __syncthreads();
        if (tid == 0) s_misc = (atomicAdd(&g_ctr[tix], 1) == NCHUNK - 1);
        __syncthreads();

        if (s_misc) {
            if (inside) {
                float Tc = 1.f, r = 0.f, g = 0.f, b = 0.f;
                #pragma unroll
                for (int s = 0; s < NCHUNK; s++) {
                    float4 v = g_seg[s * MAXPIX + pix];
                    r += Tc * v.x; g += Tc * v.y; b += Tc * v.z;
                    Tc *= v.w;
                }
                out[pix*3] = r; out[pix*3+1] = g; out[pix*3+2] = b;
            }
            __syncthreads();
            if (tid == 0) g_ctr[tix] = 0;     // reset ticket for next replay
        }
    }

    // ---- exit ticket: last block to drain the queue resets global state ----
    __syncthreads();
    if (tid == 0) {
        __threadfence();
        if (atomicAdd(&g_bar, 1) == 3 * NB - 1) {
            g_bar  = 0;
            g_work = 0;
            __threadfence();
        }
    }
}

// ---------------------------------------------------------------------------
extern "C" void kernel_launch(void* const* d_in, const int* in_sizes, int n_in,
                              void* d_out, int out_size) {
    const float* vms   = (const float*)d_in[0];  // (C,4,4)
    const float* Ks    = (const float*)d_in[1];  // (C,3,3)
    const float* means = (const float*)d_in[2];  // (N,3)
    const float* quats = (const float*)d_in[3];  // (N,4)
    const float* lsc   = (const float*)d_in[4];  // (N,3)
    const float* olog  = (const float*)d_in[5];  // (N,)
    const float* clog  = (const float*)d_in[6];  // (N,3)

    int C = in_sizes[0] / 16;
    int N = in_sizes[2] / 3;
    int HW = out_size / (3 * C);
    int W = (int)(sqrt((double)HW) + 0.5);
    int H = HW / W;
    int tilesX = (W + TILE - 1) / TILE;
    int tilesY = (H + TILE - 1) / TILE;

    k_fused<<<NB, 256>>>(vms, Ks, means, quats, lsc, olog, clog,
                         (float*)d_out, C, N, W, H, tilesX, tilesY);
}